// round 6
// baseline (speedup 1.0000x reference)
#include <cuda_runtime.h>

#define TT 512
#define CC 256
#define LL 128
#define SS 257          // 2L+1
#define NWARP 9
#define NTHREADS 288
#define PAD 16
#define EPSF 1e-7f

struct alignas(16) Smem {
    float P[3][8 * CC];       // triple-buffered groups of 8 prob rows (+eps); float4-accessed
    float A[2][PAD + SS];     // alpha, front-padded with zeros
    float wmax[2][NWARP];     // per-warp maxima, double buffered
    int   ecls[SS];
    float eskip[SS];
};

// Advance K time steps with ONE barrier. Thread s recomputes the dependency
// cone from alpha[s-2K..s] down to alpha_new[s]. Blank cells (even extended
// positions) use a broadcast blank prob; label cells gather + allow skip.
// CRITICAL: scl is applied to the cone INPUTS so intermediates stay within
// one block-decay of unity (FTZ-safe); end-scaling loses the top lanes.
template<int K>
__device__ __forceinline__ void step_block(
    Smem& sm, int srcA, int dstA, const float* Pbase,
    const int cls8[8], const float skp8[8],
    int s, int tid, int& esum,
    const float4 hold[2], bool doSts, int stsBuf,
    const float* ldgPtr, float4 fresh[2])
{
    // issue prefetch LDGs first (consumed 2 iterations from now)
    const bool doLdg = (ldgPtr != nullptr) && (tid < 256);
    if (doLdg) {
        fresh[0] = reinterpret_cast<const float4*>(ldgPtr)[tid];
        fresh[1] = reinterpret_cast<const float4*>(ldgPtr)[tid + 256];
    }

    // block max of previous iteration -> exact power-of-two rescale
    float m = sm.wmax[srcA][0];
    #pragma unroll
    for (int w = 1; w < NWARP; ++w) m = fmaxf(m, sm.wmax[srcA][w]);
    const int e = (int)(__float_as_uint(m) >> 23) - 127;
    esum += e;
    const float scl = __uint_as_float((unsigned)(127 - e) << 23);

    const bool act = (tid < SS);

    // load + rescale the 2K+1 alpha inputs (input scaling => FTZ-safe range)
    float v[2 * K + 1];
    #pragma unroll
    for (int d = 0; d <= 2 * K; ++d)
        v[d] = act ? sm.A[srcA][s + d + (PAD - 2 * K)] * scl : 0.f;

    #pragma unroll
    for (int r = 0; r < K; ++r) {
        const float* Pr = Pbase + r * CC;
        const float pb = Pr[CC - 1];          // blank prob: broadcast load
        const int w = 2 * (K - 1 - r) + 1;
        #pragma unroll
        for (int d = 0; d < w; ++d) {
            const int off = (w - 1) - d;
            const float sum2 = v[d + 1] + v[d + 2];
            const bool lab = (((s ^ off) & 1) != 0);   // label cell iff pos = s-off is odd
            const int idx = off >> 1;
            const float t = lab ? fmaf(skp8[idx], v[d], sum2) : sum2;
            const float p = lab ? Pr[cls8[idx]] : pb;
            v[d] = t * p;
        }
    }

    const float fin = act ? v[0] : 0.f;
    const unsigned wm = __reduce_max_sync(0xffffffffu, __float_as_uint(fin));
    if (act) sm.A[dstA][PAD + s] = fin;
    if ((tid & 31) == 0) sm.wmax[dstA][tid >> 5] = __uint_as_float(wm);

    // stage the group held in registers (loaded last iteration)
    if (doSts && tid < 256) {
        float4* dst = reinterpret_cast<float4*>(sm.P[stsBuf]);
        float4 a = hold[0], bb = hold[1];
        a.x += EPSF; a.y += EPSF; a.z += EPSF; a.w += EPSF;
        bb.x += EPSF; bb.y += EPSF; bb.z += EPSF; bb.w += EPSF;
        dst[tid] = a;
        dst[tid + 256] = bb;
    }
    __syncthreads();
}

__global__ __launch_bounds__(NTHREADS, 2)
void ctc_fwd8(const int* __restrict__ y_true,
              const float* __restrict__ y_pred,
              float* __restrict__ out)
{
    __shared__ Smem sm;
    const int b = blockIdx.x;
    const int tid = threadIdx.x;
    const int s = tid;
    const float* base = y_pred + (size_t)b * TT * CC;

    // ---- setup: extended label, skip flags, pads ----
    if (tid < SS) {
        int c = CC - 1; float sk = 0.f;
        if (tid & 1) {
            const int j = tid >> 1;
            c = y_true[b * LL + j];
            sk = (j >= 1 && c != y_true[b * LL + j - 1]) ? 1.f : 0.f;
        }
        sm.ecls[tid] = c;
        sm.eskip[tid] = sk;
    }
    if (tid < PAD) { sm.A[0][tid] = 0.f; sm.A[1][tid] = 0.f; }

    // stage groups 0 and 1 directly (rows 0..15)
    if (tid < 256) {
        #pragma unroll
        for (int g = 0; g < 2; ++g) {
            const float4* gp = reinterpret_cast<const float4*>(base + g * 8 * CC);
            float4* dp = reinterpret_cast<float4*>(sm.P[g]);
            #pragma unroll
            for (int q = 0; q < 2; ++q) {
                float4 v = gp[tid + q * 256];
                v.x += EPSF; v.y += EPSF; v.z += EPSF; v.w += EPSF;
                dp[tid + q * 256] = v;
            }
        }
    }
    __syncthreads();

    // per-thread label class/skip for this thread's 8 possible label offsets
    int cls8[8]; float skp8[8];
    const int par = 1 - (s & 1);      // label offsets have opposite parity of s
    #pragma unroll
    for (int i = 0; i < 8; ++i) {
        const int o = 2 * i + par;
        const int pos = s - o;
        const bool ok = (tid < SS) && (pos >= 1);
        cls8[i] = ok ? sm.ecls[pos] : 0;
        skp8[i] = ok ? sm.eskip[pos] : 0.f;
    }

    // ---- alpha0 ----
    float v0 = 0.f;
    if (tid < SS) {
        v0 = (tid < 2) ? sm.P[0][sm.ecls[tid]] : 0.f;
        sm.A[0][PAD + tid] = v0;
    }
    const unsigned wm0 = __reduce_max_sync(0xffffffffu, __float_as_uint(v0));
    if ((tid & 31) == 0) sm.wmax[0][tid >> 5] = __uint_as_float(wm0);
    __syncthreads();

    int esum = 0;
    float4 hold[2], fresh[2];

    // preload group 2 into registers
    if (tid < 256) {
        const float4* gp = reinterpret_cast<const float4*>(base + 2 * 8 * CC);
        hold[0] = gp[tid];
        hold[1] = gp[tid + 256];
    }

    // iter 0: K=7 (steps t=1..7, rows 1..7 of group 0); LDG group 3; STS group 2 -> buf 2
    step_block<7>(sm, 0, 1, sm.P[0] + CC, cls8, skp8, s, tid, esum,
                  hold, true, 2, base + (size_t)3 * 8 * CC, fresh);
    hold[0] = fresh[0]; hold[1] = fresh[1];

    // iters 1..63: K=8 (group i rows), LDG group i+3, STS group i+2 -> buf (i+2)%3
    for (int i = 1; i < 64; ++i) {
        const int srcA = i & 1;
        const int dstA = 1 - srcA;
        const float* ldg = (i <= 60) ? base + (size_t)(i + 3) * 8 * CC : nullptr;
        const bool doSts = (i <= 61);
        step_block<8>(sm, srcA, dstA, sm.P[i % 3], cls8, skp8, s, tid, esum,
                      hold, doSts, (i + 2) % 3, ldg, fresh);
        hold[0] = fresh[0]; hold[1] = fresh[1];
    }

    if (tid == 0) {
        // last iteration i=63: dstA = 0
        const float s2 = sm.A[0][PAD + SS - 1] + sm.A[0][PAD + SS - 2];
        out[b] = -(logf(s2) + 0.69314718055994530942f * (float)esum);
    }
}

extern "C" void kernel_launch(void* const* d_in, const int* in_sizes, int n_in,
                              void* d_out, int out_size)
{
    const int* yt;
    const float* yp;
    if (in_sizes[0] < in_sizes[1]) {
        yt = (const int*)d_in[0];
        yp = (const float*)d_in[1];
    } else {
        yt = (const int*)d_in[1];
        yp = (const float*)d_in[0];
    }
    ctc_fwd8<<<256, NTHREADS>>>(yt, yp, (float*)d_out);
}